// round 6
// baseline (speedup 1.0000x reference)
#include <cuda_runtime.h>
#include <cuda_bf16.h>

#define NN 100000
#define NE 3200000
#define NG 512
#define IN_DIM 29
#define HID 128
#define LAT 256

// ---------------- scratch (device globals; no allocation allowed) -------------
__device__ float g_deg[NN];
__device__ float g_dis[NN];
__device__ float g_h[NN * HID];     // layer input (post-relu)
__device__ float g_hw[NN * HID];    // h @ W
__device__ float g_agg[NN * HID];   // aggregation buffer
__device__ float g_sums[NG * HID];
__device__ float g_cnts[NG];
__device__ float g_pooled[NG * HID];

// ---------------- small utility kernels --------------------------------------
__global__ void k_zero_deg() {
    int i = blockIdx.x * blockDim.x + threadIdx.x;
    if (i < NN) g_deg[i] = 0.0f;
}

__global__ void k_zero_pool() {
    int i = blockIdx.x * blockDim.x + threadIdx.x;
    if (i < NG * HID) g_sums[i] = 0.0f;
    if (i < NG) g_cnts[i] = 0.0f;
}

__global__ void k_count(const int* __restrict__ dst) {
    int e = blockIdx.x * blockDim.x + threadIdx.x;
    if (e < NE) atomicAdd(&g_deg[dst[e]], 1.0f);
}

__global__ void k_dis() {
    int i = blockIdx.x * blockDim.x + threadIdx.x;
    if (i < NN) g_dis[i] = rsqrtf(g_deg[i] + 1.0f);
}

// ---------------- GEMM: x[NN,29] @ W1[29,128] -> g_hw ------------------------
__global__ void k_gemm_in(const float* __restrict__ x, const float* __restrict__ W) {
    __shared__ float Ws[IN_DIM * HID];
    for (int i = threadIdx.x; i < IN_DIM * HID; i += blockDim.x) Ws[i] = W[i];
    __syncthreads();
    int warp = threadIdx.x >> 5, lane = threadIdx.x & 31;
    int node = blockIdx.x * 8 + warp;
    if (node >= NN) return;
    float acc0 = 0.f, acc1 = 0.f, acc2 = 0.f, acc3 = 0.f;
    const float* xr = x + node * IN_DIM;
    #pragma unroll
    for (int k = 0; k < IN_DIM; k++) {
        float xv = __ldg(xr + k);
        const float* wr = Ws + k * HID + lane;
        acc0 += xv * wr[0];
        acc1 += xv * wr[32];
        acc2 += xv * wr[64];
        acc3 += xv * wr[96];
    }
    float* o = g_hw + node * HID + lane;
    o[0] = acc0; o[32] = acc1; o[64] = acc2; o[96] = acc3;
}

// ---------------- GEMM: g_h[NN,128] @ W[128,128] -> g_hw ----------------------
__global__ void k_gemm_hid(const float* __restrict__ W) {
    int warp = threadIdx.x >> 5, lane = threadIdx.x & 31;
    int node = blockIdx.x * 8 + warp;
    if (node >= NN) return;
    const float* hr = g_h + node * HID;
    float hv0 = hr[lane], hv1 = hr[lane + 32], hv2 = hr[lane + 64], hv3 = hr[lane + 96];
    float acc0 = 0.f, acc1 = 0.f, acc2 = 0.f, acc3 = 0.f;
    #pragma unroll 4
    for (int k = 0; k < HID; k++) {
        int sel = k >> 5;
        float src = (sel == 0) ? hv0 : (sel == 1) ? hv1 : (sel == 2) ? hv2 : hv3;
        float hk = __shfl_sync(0xffffffffu, src, k & 31);
        const float* wr = W + k * HID + lane;
        acc0 += hk * __ldg(wr);
        acc1 += hk * __ldg(wr + 32);
        acc2 += hk * __ldg(wr + 64);
        acc3 += hk * __ldg(wr + 96);
    }
    float* o = g_hw + node * HID + lane;
    o[0] = acc0; o[32] = acc1; o[64] = acc2; o[96] = acc3;
}

// ---------------- agg = hw * dis^2 + b  (self-loop term + bias) ---------------
__global__ void k_init(const float* __restrict__ b) {
    int i = blockIdx.x * blockDim.x + threadIdx.x;
    if (i < NN * HID) {
        int node = i >> 7, c = i & 127;
        float d = g_dis[node];
        g_agg[i] = g_hw[i] * d * d + __ldg(b + c);
    }
}

// ---------------- edge scatter: agg[dst] += hw[src] * dis[src]*dis[dst] -------
__global__ void k_scatter(const int* __restrict__ src,
                          const int* __restrict__ dst) {
    int e = (blockIdx.x * blockDim.x + threadIdx.x) >> 5;
    int lane = threadIdx.x & 31;
    if (e >= NE) return;
    int s = src[e];
    int d = dst[e];
    float n = g_dis[s] * g_dis[d];
    const float* hs = g_hw + s * HID + lane;
    float* ad = g_agg + d * HID + lane;
    atomicAdd(ad,      __ldg(hs)      * n);
    atomicAdd(ad + 32, __ldg(hs + 32) * n);
    atomicAdd(ad + 64, __ldg(hs + 64) * n);
    atomicAdd(ad + 96, __ldg(hs + 96) * n);
}

// ---------------- relu: g_h = max(agg, 0) -------------------------------------
__global__ void k_relu() {
    int i = blockIdx.x * blockDim.x + threadIdx.x;
    if (i < NN * HID) g_h[i] = fmaxf(g_agg[i], 0.0f);
}

// ---------------- pooling (batch is sorted: run-length local accumulate) ------
__global__ void k_pool(const int* __restrict__ batch) {
    const int CH = 128;                   // nodes per block
    int base = blockIdx.x * CH;
    int c = threadIdx.x;                  // column 0..127
    float acc = 0.0f;
    int cur = -1;
    for (int i = 0; i < CH; i++) {
        int node = base + i;
        if (node >= NN) break;
        int g = __ldg(batch + node);
        if (g != cur) {
            if (cur >= 0) atomicAdd(&g_sums[cur * HID + c], acc);
            cur = g; acc = 0.0f;
        }
        acc += g_h[node * HID + c];
    }
    if (cur >= 0) atomicAdd(&g_sums[cur * HID + c], acc);

    if (threadIdx.x == 0) {
        int cur2 = -1; float cnt = 0.0f;
        for (int i = 0; i < CH; i++) {
            int node = base + i;
            if (node >= NN) break;
            int g = __ldg(batch + node);
            if (g != cur2) {
                if (cur2 >= 0) atomicAdd(&g_cnts[cur2], cnt);
                cur2 = g; cnt = 0.0f;
            }
            cnt += 1.0f;
        }
        if (cur2 >= 0) atomicAdd(&g_cnts[cur2], cnt);
    }
}

__global__ void k_pooldiv() {
    int i = blockIdx.x * blockDim.x + threadIdx.x;
    if (i < NG * HID) {
        int g = i >> 7;
        g_pooled[i] = g_sums[i] / fmaxf(g_cnts[g], 1.0f);
    }
}

// ---------------- heads: mu = pooled@Wmu+bmu ; logvar = pooled@Wlv+blv --------
__global__ void k_head(const float* __restrict__ Wmu, const float* __restrict__ bmu,
                       const float* __restrict__ Wlv, const float* __restrict__ blv,
                       float* __restrict__ out) {
    int g = blockIdx.x;       // 0..511
    __shared__ float p[HID];
    for (int i = threadIdx.x; i < HID; i += blockDim.x) p[i] = g_pooled[g * HID + i];
    __syncthreads();
    int c = threadIdx.x;      // 0..255
    float am = __ldg(bmu + c);
    float al = __ldg(blv + c);
    #pragma unroll 8
    for (int k = 0; k < HID; k++) {
        float pv = p[k];
        am += pv * __ldg(Wmu + k * LAT + c);
        al += pv * __ldg(Wlv + k * LAT + c);
    }
    out[g * LAT + c] = am;
    out[NG * LAT + g * LAT + c] = al;
}

// ---------------- launcher ----------------------------------------------------
extern "C" void kernel_launch(void* const* d_in, const int* in_sizes, int n_in,
                              void* d_out, int out_size) {
    const float* x    = (const float*)d_in[0];
    const int*   ei   = (const int*)d_in[1];   // [2, NE] int32
    const int*   bat  = (const int*)d_in[2];   // [NN] int32
    const float* W1   = (const float*)d_in[3];
    const float* b1   = (const float*)d_in[4];
    const float* W2   = (const float*)d_in[5];
    const float* b2   = (const float*)d_in[6];
    const float* W3   = (const float*)d_in[7];
    const float* b3   = (const float*)d_in[8];
    const float* Wmu  = (const float*)d_in[9];
    const float* bmu  = (const float*)d_in[10];
    const float* Wlv  = (const float*)d_in[11];
    const float* blv  = (const float*)d_in[12];
    float* out = (float*)d_out;

    const int* src = ei;
    const int* dst = ei + NE;

    const int T = 256;

    // degrees + normalization
    k_zero_deg<<<(NN + T - 1) / T, T>>>();
    k_count<<<(NE + T - 1) / T, T>>>(dst);
    k_dis<<<(NN + T - 1) / T, T>>>();

    const int gemm_blocks = (NN + 7) / 8;
    const int feat_blocks = (NN * HID + T - 1) / T;
    const int edge_blocks = (NE * 32 + T - 1) / T;

    // layer 1 (input 29 -> 128)
    k_gemm_in<<<gemm_blocks, T>>>(x, W1);
    k_init<<<feat_blocks, T>>>(b1);
    k_scatter<<<edge_blocks, T>>>(src, dst);
    k_relu<<<feat_blocks, T>>>();

    // layer 2
    k_gemm_hid<<<gemm_blocks, T>>>(W2);
    k_init<<<feat_blocks, T>>>(b2);
    k_scatter<<<edge_blocks, T>>>(src, dst);
    k_relu<<<feat_blocks, T>>>();

    // layer 3
    k_gemm_hid<<<gemm_blocks, T>>>(W3);
    k_init<<<feat_blocks, T>>>(b3);
    k_scatter<<<edge_blocks, T>>>(src, dst);
    k_relu<<<feat_blocks, T>>>();

    // pooling
    k_zero_pool<<<(NG * HID + T - 1) / T, T>>>();
    k_pool<<<(NN + 127) / 128, HID>>>(bat);
    k_pooldiv<<<(NG * HID + T - 1) / T, T>>>();

    // heads
    k_head<<<NG, LAT>>>(Wmu, bmu, Wlv, blv, out);
}

// round 9
// speedup vs baseline: 1.9623x; 1.9623x over previous
#include <cuda_runtime.h>
#include <cuda_bf16.h>

#define NN 100000
#define NE 3200000
#define NG 512
#define IN_DIM 29
#define HID 128
#define LAT 256

#define SCAN_B 512
#define NBLK ((NN + SCAN_B - 1) / SCAN_B)   // 196

// ---------------- scratch (device globals; no allocation allowed) -------------
__device__ float g_dis[NN];
__device__ int   g_indeg[NN];
__device__ int   g_rowptr[NN + 1];
__device__ int   g_fill[NN];
__device__ int   g_col[NE];     // CSR: source node per incoming edge
__device__ float g_wt[NE];      // CSR: dis[src]*dis[dst] per incoming edge
__device__ int   g_bsum[NBLK];

__device__ float g_h[NN * HID];     // layer input (post-relu)
__device__ float g_hw[NN * HID];    // h @ W
__device__ float g_sums[NG * HID];
__device__ float g_cnts[NG];
__device__ float g_pooled[NG * HID];

// ---------------- CSR build ---------------------------------------------------
__global__ void k_zero_deg() {
    int i = blockIdx.x * blockDim.x + threadIdx.x;
    if (i < NN) g_indeg[i] = 0;
}

__global__ void k_count(const int* __restrict__ dst) {
    int e = blockIdx.x * blockDim.x + threadIdx.x;
    if (e < NE) atomicAdd(&g_indeg[dst[e]], 1);
}

__global__ void k_dis() {   // also zeroes fill counters
    int i = blockIdx.x * blockDim.x + threadIdx.x;
    if (i < NN) {
        g_dis[i] = rsqrtf((float)g_indeg[i] + 1.0f);
        g_fill[i] = 0;
    }
}

// two-level exclusive scan of g_indeg -> g_rowptr
__global__ void k_scan1() {
    __shared__ int sh[SCAN_B];
    int tid = threadIdx.x;
    int idx = blockIdx.x * SCAN_B + tid;
    int v = (idx < NN) ? g_indeg[idx] : 0;
    sh[tid] = v;
    __syncthreads();
    for (int off = 1; off < SCAN_B; off <<= 1) {
        int t = (tid >= off) ? sh[tid - off] : 0;
        __syncthreads();
        sh[tid] += t;
        __syncthreads();
    }
    if (idx < NN) g_rowptr[idx] = sh[tid] - v;   // exclusive within block
    if (tid == SCAN_B - 1) g_bsum[blockIdx.x] = sh[tid];
}

__global__ void k_scan2() {
    if (threadIdx.x == 0 && blockIdx.x == 0) {
        int run = 0;
        for (int i = 0; i < NBLK; i++) {
            int t = g_bsum[i];
            g_bsum[i] = run;
            run += t;
        }
    }
}

__global__ void k_scan3() {
    int idx = blockIdx.x * SCAN_B + threadIdx.x;
    if (idx < NN) g_rowptr[idx] += g_bsum[blockIdx.x];
    if (idx == 0) g_rowptr[NN] = NE;
}

__global__ void k_fill(const int* __restrict__ src, const int* __restrict__ dst) {
    int e = blockIdx.x * blockDim.x + threadIdx.x;
    if (e >= NE) return;
    int s = src[e];
    int d = dst[e];
    int pos = g_rowptr[d] + atomicAdd(&g_fill[d], 1);
    g_col[pos] = s;
    g_wt[pos]  = g_dis[s] * g_dis[d];
}

// ---------------- GEMM: x[NN,29] @ W1[29,128] -> g_hw ------------------------
__global__ void k_gemm_in(const float* __restrict__ x, const float* __restrict__ W) {
    __shared__ float Ws[IN_DIM * HID];
    for (int i = threadIdx.x; i < IN_DIM * HID; i += blockDim.x) Ws[i] = W[i];
    __syncthreads();
    int warp = threadIdx.x >> 5, lane = threadIdx.x & 31;
    int node = blockIdx.x * 8 + warp;
    if (node >= NN) return;
    float acc0 = 0.f, acc1 = 0.f, acc2 = 0.f, acc3 = 0.f;
    const float* xr = x + node * IN_DIM;
    #pragma unroll
    for (int k = 0; k < IN_DIM; k++) {
        float xv = __ldg(xr + k);
        const float* wr = Ws + k * HID + lane;
        acc0 += xv * wr[0];
        acc1 += xv * wr[32];
        acc2 += xv * wr[64];
        acc3 += xv * wr[96];
    }
    float* o = g_hw + node * HID + lane;
    o[0] = acc0; o[32] = acc1; o[64] = acc2; o[96] = acc3;
}

// ---------------- GEMM: g_h[NN,128] @ W[128,128] -> g_hw ----------------------
__global__ void k_gemm_hid(const float* __restrict__ W) {
    int warp = threadIdx.x >> 5, lane = threadIdx.x & 31;
    int node = blockIdx.x * 8 + warp;
    if (node >= NN) return;
    const float* hr = g_h + node * HID;
    float hv0 = hr[lane], hv1 = hr[lane + 32], hv2 = hr[lane + 64], hv3 = hr[lane + 96];
    float acc0 = 0.f, acc1 = 0.f, acc2 = 0.f, acc3 = 0.f;
    #pragma unroll 4
    for (int k = 0; k < HID; k++) {
        int sel = k >> 5;
        float s = (sel == 0) ? hv0 : (sel == 1) ? hv1 : (sel == 2) ? hv2 : hv3;
        float hk = __shfl_sync(0xffffffffu, s, k & 31);
        const float* wr = W + k * HID + lane;
        acc0 += hk * __ldg(wr);
        acc1 += hk * __ldg(wr + 32);
        acc2 += hk * __ldg(wr + 64);
        acc3 += hk * __ldg(wr + 96);
    }
    float* o = g_hw + node * HID + lane;
    o[0] = acc0; o[32] = acc1; o[64] = acc2; o[96] = acc3;
}

// ------- fused gather: g_h[d] = relu( sum_j w_j*hw[col_j] + dis^2*hw[d] + b ) --
__global__ void k_gather(const float* __restrict__ b) {
    int warp = threadIdx.x >> 5, lane = threadIdx.x & 31;
    int node = blockIdx.x * 8 + warp;
    if (node >= NN) return;
    const float4* hw4 = (const float4*)g_hw;

    float dd = g_dis[node];
    dd *= dd;
    float4 self = hw4[node * 32 + lane];
    float4 bb = __ldg(((const float4*)b) + lane);
    float a0 = self.x * dd + bb.x;
    float a1 = self.y * dd + bb.y;
    float a2 = self.z * dd + bb.z;
    float a3 = self.w * dd + bb.w;

    int beg = g_rowptr[node], end = g_rowptr[node + 1];
    int j = beg;
    for (; j + 1 < end; j += 2) {
        int   s0 = __ldg(g_col + j);
        float w0 = __ldg(g_wt + j);
        int   s1 = __ldg(g_col + j + 1);
        float w1 = __ldg(g_wt + j + 1);
        float4 v0 = hw4[s0 * 32 + lane];
        float4 v1 = hw4[s1 * 32 + lane];
        a0 += w0 * v0.x + w1 * v1.x;
        a1 += w0 * v0.y + w1 * v1.y;
        a2 += w0 * v0.z + w1 * v1.z;
        a3 += w0 * v0.w + w1 * v1.w;
    }
    if (j < end) {
        int   s0 = __ldg(g_col + j);
        float w0 = __ldg(g_wt + j);
        float4 v0 = hw4[s0 * 32 + lane];
        a0 += w0 * v0.x;
        a1 += w0 * v0.y;
        a2 += w0 * v0.z;
        a3 += w0 * v0.w;
    }

    float4 o;
    o.x = fmaxf(a0, 0.0f);
    o.y = fmaxf(a1, 0.0f);
    o.z = fmaxf(a2, 0.0f);
    o.w = fmaxf(a3, 0.0f);
    ((float4*)g_h)[node * 32 + lane] = o;
}

// ---------------- pooling (batch is sorted: run-length local accumulate) ------
__global__ void k_zero_pool() {
    int i = blockIdx.x * blockDim.x + threadIdx.x;
    if (i < NG * HID) g_sums[i] = 0.0f;
    if (i < NG) g_cnts[i] = 0.0f;
}

__global__ void k_pool(const int* __restrict__ batch) {
    const int CH = 128;                   // nodes per block
    int base = blockIdx.x * CH;
    int c = threadIdx.x;                  // column 0..127
    float acc = 0.0f;
    int cur = -1;
    for (int i = 0; i < CH; i++) {
        int node = base + i;
        if (node >= NN) break;
        int g = __ldg(batch + node);
        if (g != cur) {
            if (cur >= 0) atomicAdd(&g_sums[cur * HID + c], acc);
            cur = g; acc = 0.0f;
        }
        acc += g_h[node * HID + c];
    }
    if (cur >= 0) atomicAdd(&g_sums[cur * HID + c], acc);

    if (threadIdx.x == 0) {
        int cur2 = -1; float cnt = 0.0f;
        for (int i = 0; i < CH; i++) {
            int node = base + i;
            if (node >= NN) break;
            int g = __ldg(batch + node);
            if (g != cur2) {
                if (cur2 >= 0) atomicAdd(&g_cnts[cur2], cnt);
                cur2 = g; cnt = 0.0f;
            }
            cnt += 1.0f;
        }
        if (cur2 >= 0) atomicAdd(&g_cnts[cur2], cnt);
    }
}

__global__ void k_pooldiv() {
    int i = blockIdx.x * blockDim.x + threadIdx.x;
    if (i < NG * HID) {
        int g = i >> 7;
        g_pooled[i] = g_sums[i] / fmaxf(g_cnts[g], 1.0f);
    }
}

// ---------------- heads: mu = pooled@Wmu+bmu ; logvar = pooled@Wlv+blv --------
__global__ void k_head(const float* __restrict__ Wmu, const float* __restrict__ bmu,
                       const float* __restrict__ Wlv, const float* __restrict__ blv,
                       float* __restrict__ out) {
    int g = blockIdx.x;       // 0..511
    __shared__ float p[HID];
    for (int i = threadIdx.x; i < HID; i += blockDim.x) p[i] = g_pooled[g * HID + i];
    __syncthreads();
    int c = threadIdx.x;      // 0..255
    float am = __ldg(bmu + c);
    float al = __ldg(blv + c);
    #pragma unroll 8
    for (int k = 0; k < HID; k++) {
        float pv = p[k];
        am += pv * __ldg(Wmu + k * LAT + c);
        al += pv * __ldg(Wlv + k * LAT + c);
    }
    out[g * LAT + c] = am;
    out[NG * LAT + g * LAT + c] = al;
}

// ---------------- launcher ----------------------------------------------------
extern "C" void kernel_launch(void* const* d_in, const int* in_sizes, int n_in,
                              void* d_out, int out_size) {
    const float* x    = (const float*)d_in[0];
    const int*   ei   = (const int*)d_in[1];   // [2, NE] int32
    const int*   bat  = (const int*)d_in[2];   // [NN] int32
    const float* W1   = (const float*)d_in[3];
    const float* b1   = (const float*)d_in[4];
    const float* W2   = (const float*)d_in[5];
    const float* b2   = (const float*)d_in[6];
    const float* W3   = (const float*)d_in[7];
    const float* b3   = (const float*)d_in[8];
    const float* Wmu  = (const float*)d_in[9];
    const float* bmu  = (const float*)d_in[10];
    const float* Wlv  = (const float*)d_in[11];
    const float* blv  = (const float*)d_in[12];
    float* out = (float*)d_out;

    const int* src = ei;
    const int* dst = ei + NE;

    const int T = 256;
    const int node_blocks = (NN + T - 1) / T;
    const int edge_blocks = (NE + T - 1) / T;
    const int warp8_blocks = (NN + 7) / 8;

    // ---- CSR build (per launch; deterministic work) ----
    k_zero_deg<<<node_blocks, T>>>();
    k_count<<<edge_blocks, T>>>(dst);
    k_dis<<<node_blocks, T>>>();
    k_scan1<<<NBLK, SCAN_B>>>();
    k_scan2<<<1, 32>>>();
    k_scan3<<<NBLK, SCAN_B>>>();
    k_fill<<<edge_blocks, T>>>(src, dst);

    // ---- layer 1 (29 -> 128) ----
    k_gemm_in<<<warp8_blocks, T>>>(x, W1);
    k_gather<<<warp8_blocks, T>>>(b1);

    // ---- layer 2 ----
    k_gemm_hid<<<warp8_blocks, T>>>(W2);
    k_gather<<<warp8_blocks, T>>>(b2);

    // ---- layer 3 ----
    k_gemm_hid<<<warp8_blocks, T>>>(W3);
    k_gather<<<warp8_blocks, T>>>(b3);

    // ---- pooling ----
    k_zero_pool<<<(NG * HID + T - 1) / T, T>>>();
    k_pool<<<(NN + 127) / 128, HID>>>(bat);
    k_pooldiv<<<(NG * HID + T - 1) / T, T>>>();

    // ---- heads ----
    k_head<<<NG, LAT>>>(Wmu, bmu, Wlv, blv, out);
}

// round 12
// speedup vs baseline: 3.1185x; 1.5893x over previous
#include <cuda_runtime.h>
#include <cuda_bf16.h>

#define NN 100000
#define NE 3200000
#define NG 512
#define IN_DIM 29
#define HID 128
#define LAT 256

#define SCAN_B 512
#define NBLK ((NN + SCAN_B - 1) / SCAN_B)   // 196
#define TN 64                                // GEMM node tile

// ---------------- scratch (device globals; no allocation allowed) -------------
__device__ float g_dis[NN];
__device__ int   g_indeg[NN];
__device__ int   g_rowptr[NN + 1];
__device__ int   g_fill[NN];
__device__ int   g_col[NE];     // CSR: source node per incoming edge
__device__ float g_wt[NE];      // CSR: dis[src]*dis[dst] per incoming edge
__device__ int   g_bsum[NBLK];

__device__ float g_h[NN * HID];               // layer input (post-relu)
__device__ float g_hw[NN * HID];              // h @ W  (fp32, self-loop term)
__device__ __nv_bfloat162 g_hwh[NN * 64];     // h @ W  (bf16, neighbor gathers)
__device__ float g_sums[NG * HID];
__device__ float g_cnts[NG];
__device__ float g_pooled[NG * HID];

// ---------------- CSR build ---------------------------------------------------
__global__ void k_zero_deg() {
    int i = blockIdx.x * blockDim.x + threadIdx.x;
    if (i < NN) g_indeg[i] = 0;
}

__global__ void k_count(const int* __restrict__ dst) {
    int e = blockIdx.x * blockDim.x + threadIdx.x;
    if (e < NE) atomicAdd(&g_indeg[dst[e]], 1);
}

__global__ void k_dis() {   // also zeroes fill counters
    int i = blockIdx.x * blockDim.x + threadIdx.x;
    if (i < NN) {
        g_dis[i] = rsqrtf((float)g_indeg[i] + 1.0f);
        g_fill[i] = 0;
    }
}

__global__ void k_scan1() {
    __shared__ int sh[SCAN_B];
    int tid = threadIdx.x;
    int idx = blockIdx.x * SCAN_B + tid;
    int v = (idx < NN) ? g_indeg[idx] : 0;
    sh[tid] = v;
    __syncthreads();
    for (int off = 1; off < SCAN_B; off <<= 1) {
        int t = (tid >= off) ? sh[tid - off] : 0;
        __syncthreads();
        sh[tid] += t;
        __syncthreads();
    }
    if (idx < NN) g_rowptr[idx] = sh[tid] - v;
    if (tid == SCAN_B - 1) g_bsum[blockIdx.x] = sh[tid];
}

__global__ void k_scan2() {
    if (threadIdx.x == 0 && blockIdx.x == 0) {
        int run = 0;
        for (int i = 0; i < NBLK; i++) {
            int t = g_bsum[i];
            g_bsum[i] = run;
            run += t;
        }
    }
}

__global__ void k_scan3() {
    int idx = blockIdx.x * SCAN_B + threadIdx.x;
    if (idx < NN) g_rowptr[idx] += g_bsum[blockIdx.x];
    if (idx == 0) g_rowptr[NN] = NE;
}

__global__ void k_fill(const int* __restrict__ src, const int* __restrict__ dst) {
    int e = blockIdx.x * blockDim.x + threadIdx.x;
    if (e >= NE) return;
    int s = src[e];
    int d = dst[e];
    int pos = g_rowptr[d] + atomicAdd(&g_fill[d], 1);
    g_col[pos] = s;
    g_wt[pos]  = g_dis[s] * g_dis[d];
}

// ---------------- epilogue helper: store fp32 + bf16 copies -------------------
__device__ __forceinline__ void store_hw(int node, int cg, float4 a) {
    ((float4*)g_hw)[node * 32 + cg] = a;
    g_hwh[node * 64 + cg * 2 + 0] = __float22bfloat162_rn(make_float2(a.x, a.y));
    g_hwh[node * 64 + cg * 2 + 1] = __float22bfloat162_rn(make_float2(a.z, a.w));
}

// ---------------- tiled GEMM: x[NN,29] @ W1[29,128] -> g_hw/g_hwh -------------
__global__ void k_gemm_in_t(const float* __restrict__ x, const float* __restrict__ W) {
    __shared__ float Hs[IN_DIM][TN];
    int base = blockIdx.x * TN;
    int t = threadIdx.x;
    for (int id = t; id < TN * IN_DIM; id += 256) {
        int n = id & 63;
        int kk = id >> 6;
        int node = base + n;
        Hs[kk][n] = (node < NN) ? __ldg(x + node * IN_DIM + kk) : 0.0f;
    }
    __syncthreads();

    int cg = t & 31;   // col quad (cols 4*cg..4*cg+3)
    int ng = t >> 5;   // node group (nodes ng*8..ng*8+7)
    float4 acc[8] = {};
    const float4* W4 = (const float4*)W;
    #pragma unroll
    for (int k = 0; k < IN_DIM; k++) {
        float4 w = __ldg(W4 + k * 32 + cg);
        float hk[8];
        *(float4*)&hk[0] = *(const float4*)&Hs[k][ng * 8];
        *(float4*)&hk[4] = *(const float4*)&Hs[k][ng * 8 + 4];
        #pragma unroll
        for (int i = 0; i < 8; i++) {
            acc[i].x += hk[i] * w.x;
            acc[i].y += hk[i] * w.y;
            acc[i].z += hk[i] * w.z;
            acc[i].w += hk[i] * w.w;
        }
    }
    #pragma unroll
    for (int i = 0; i < 8; i++) {
        int node = base + ng * 8 + i;
        if (node < NN) store_hw(node, cg, acc[i]);
    }
}

// ---------------- tiled GEMM: g_h[NN,128] @ W[128,128] -> g_hw/g_hwh ----------
__global__ void k_gemm_hid_t(const float* __restrict__ W) {
    __shared__ float Hs[HID][TN];
    int base = blockIdx.x * TN;
    int t = threadIdx.x;
    // load h tile transposed: Hs[k][n] = g_h[base+n][k]
    for (int id = t; id < TN * 32; id += 256) {    // 2048 float4
        int n = id & 63;
        int k4 = id >> 6;                           // 0..31
        int node = base + n;
        float4 v = (node < NN) ? ((const float4*)g_h)[node * 32 + k4]
                               : make_float4(0.f, 0.f, 0.f, 0.f);
        Hs[k4 * 4 + 0][n] = v.x;
        Hs[k4 * 4 + 1][n] = v.y;
        Hs[k4 * 4 + 2][n] = v.z;
        Hs[k4 * 4 + 3][n] = v.w;
    }
    __syncthreads();

    int cg = t & 31;
    int ng = t >> 5;
    float4 acc[8] = {};
    const float4* W4 = (const float4*)W;
    #pragma unroll 4
    for (int k = 0; k < HID; k++) {
        float4 w = __ldg(W4 + k * 32 + cg);
        float hk[8];
        *(float4*)&hk[0] = *(const float4*)&Hs[k][ng * 8];
        *(float4*)&hk[4] = *(const float4*)&Hs[k][ng * 8 + 4];
        #pragma unroll
        for (int i = 0; i < 8; i++) {
            acc[i].x += hk[i] * w.x;
            acc[i].y += hk[i] * w.y;
            acc[i].z += hk[i] * w.z;
            acc[i].w += hk[i] * w.w;
        }
    }
    #pragma unroll
    for (int i = 0; i < 8; i++) {
        int node = base + ng * 8 + i;
        if (node < NN) store_hw(node, cg, acc[i]);
    }
}

// ------- fused gather: g_h[d] = relu( sum_j w_j*hw[col_j] + dis^2*hw[d] + b ) --
// neighbor rows read in bf16 (halved L2 traffic); self term + accumulate in fp32
__global__ void k_gather(const float* __restrict__ b) {
    int warp = threadIdx.x >> 5, lane = threadIdx.x & 31;
    int node = blockIdx.x * 8 + warp;
    if (node >= NN) return;

    float dd = g_dis[node];
    dd *= dd;
    float4 self = ((const float4*)g_hw)[node * 32 + lane];
    float4 bb = __ldg(((const float4*)b) + lane);
    float a0 = self.x * dd + bb.x;
    float a1 = self.y * dd + bb.y;
    float a2 = self.z * dd + bb.z;
    float a3 = self.w * dd + bb.w;

    const uint2* hwB = (const uint2*)g_hwh;   // 32 uint2 per row (128 bf16)
    int beg = g_rowptr[node], end = g_rowptr[node + 1];
    int j = beg;
    for (; j + 1 < end; j += 2) {
        int   s0 = __ldg(g_col + j);
        float w0 = __ldg(g_wt + j);
        int   s1 = __ldg(g_col + j + 1);
        float w1 = __ldg(g_wt + j + 1);
        uint2 u0 = hwB[s0 * 32 + lane];
        uint2 u1 = hwB[s1 * 32 + lane];
        float2 f00 = __bfloat1622float2(*(const __nv_bfloat162*)&u0.x);
        float2 f01 = __bfloat1622float2(*(const __nv_bfloat162*)&u0.y);
        float2 f10 = __bfloat1622float2(*(const __nv_bfloat162*)&u1.x);
        float2 f11 = __bfloat1622float2(*(const __nv_bfloat162*)&u1.y);
        a0 += w0 * f00.x + w1 * f10.x;
        a1 += w0 * f00.y + w1 * f10.y;
        a2 += w0 * f01.x + w1 * f11.x;
        a3 += w0 * f01.y + w1 * f11.y;
    }
    if (j < end) {
        int   s0 = __ldg(g_col + j);
        float w0 = __ldg(g_wt + j);
        uint2 u0 = hwB[s0 * 32 + lane];
        float2 f00 = __bfloat1622float2(*(const __nv_bfloat162*)&u0.x);
        float2 f01 = __bfloat1622float2(*(const __nv_bfloat162*)&u0.y);
        a0 += w0 * f00.x;
        a1 += w0 * f00.y;
        a2 += w0 * f01.x;
        a3 += w0 * f01.y;
    }

    float4 o;
    o.x = fmaxf(a0, 0.0f);
    o.y = fmaxf(a1, 0.0f);
    o.z = fmaxf(a2, 0.0f);
    o.w = fmaxf(a3, 0.0f);
    ((float4*)g_h)[node * 32 + lane] = o;
}

// ---------------- pooling (batch is sorted: run-length local accumulate) ------
__global__ void k_zero_pool() {
    int i = blockIdx.x * blockDim.x + threadIdx.x;
    if (i < NG * HID) g_sums[i] = 0.0f;
    if (i < NG) g_cnts[i] = 0.0f;
}

__global__ void k_pool(const int* __restrict__ batch) {
    const int CH = 128;
    int base = blockIdx.x * CH;
    int c = threadIdx.x;
    float acc = 0.0f;
    int cur = -1;
    for (int i = 0; i < CH; i++) {
        int node = base + i;
        if (node >= NN) break;
        int g = __ldg(batch + node);
        if (g != cur) {
            if (cur >= 0) atomicAdd(&g_sums[cur * HID + c], acc);
            cur = g; acc = 0.0f;
        }
        acc += g_h[node * HID + c];
    }
    if (cur >= 0) atomicAdd(&g_sums[cur * HID + c], acc);

    if (threadIdx.x == 0) {
        int cur2 = -1; float cnt = 0.0f;
        for (int i = 0; i < CH; i++) {
            int node = base + i;
            if (node >= NN) break;
            int g = __ldg(batch + node);
            if (g != cur2) {
                if (cur2 >= 0) atomicAdd(&g_cnts[cur2], cnt);
                cur2 = g; cnt = 0.0f;
            }
            cnt += 1.0f;
        }
        if (cur2 >= 0) atomicAdd(&g_cnts[cur2], cnt);
    }
}

__global__ void k_pooldiv() {
    int i = blockIdx.x * blockDim.x + threadIdx.x;
    if (i < NG * HID) {
        int g = i >> 7;
        g_pooled[i] = g_sums[i] / fmaxf(g_cnts[g], 1.0f);
    }
}

// ---------------- heads: mu = pooled@Wmu+bmu ; logvar = pooled@Wlv+blv --------
__global__ void k_head(const float* __restrict__ Wmu, const float* __restrict__ bmu,
                       const float* __restrict__ Wlv, const float* __restrict__ blv,
                       float* __restrict__ out) {
    int g = blockIdx.x;
    __shared__ float p[HID];
    for (int i = threadIdx.x; i < HID; i += blockDim.x) p[i] = g_pooled[g * HID + i];
    __syncthreads();
    int c = threadIdx.x;
    float am = __ldg(bmu + c);
    float al = __ldg(blv + c);
    #pragma unroll 8
    for (int k = 0; k < HID; k++) {
        float pv = p[k];
        am += pv * __ldg(Wmu + k * LAT + c);
        al += pv * __ldg(Wlv + k * LAT + c);
    }
    out[g * LAT + c] = am;
    out[NG * LAT + g * LAT + c] = al;
}

// ---------------- launcher ----------------------------------------------------
extern "C" void kernel_launch(void* const* d_in, const int* in_sizes, int n_in,
                              void* d_out, int out_size) {
    const float* x    = (const float*)d_in[0];
    const int*   ei   = (const int*)d_in[1];   // [2, NE] int32
    const int*   bat  = (const int*)d_in[2];   // [NN] int32
    const float* W1   = (const float*)d_in[3];
    const float* b1   = (const float*)d_in[4];
    const float* W2   = (const float*)d_in[5];
    const float* b2   = (const float*)d_in[6];
    const float* W3   = (const float*)d_in[7];
    const float* b3   = (const float*)d_in[8];
    const float* Wmu  = (const float*)d_in[9];
    const float* bmu  = (const float*)d_in[10];
    const float* Wlv  = (const float*)d_in[11];
    const float* blv  = (const float*)d_in[12];
    float* out = (float*)d_out;

    const int* src = ei;
    const int* dst = ei + NE;

    const int T = 256;
    const int node_blocks = (NN + T - 1) / T;
    const int edge_blocks = (NE + T - 1) / T;
    const int warp8_blocks = (NN + 7) / 8;
    const int tile_blocks = (NN + TN - 1) / TN;

    // ---- CSR build ----
    k_zero_deg<<<node_blocks, T>>>();
    k_count<<<edge_blocks, T>>>(dst);
    k_dis<<<node_blocks, T>>>();
    k_scan1<<<NBLK, SCAN_B>>>();
    k_scan2<<<1, 32>>>();
    k_scan3<<<NBLK, SCAN_B>>>();
    k_fill<<<edge_blocks, T>>>(src, dst);

    // ---- layer 1 (29 -> 128) ----
    k_gemm_in_t<<<tile_blocks, T>>>(x, W1);
    k_gather<<<warp8_blocks, T>>>(b1);

    // ---- layer 2 ----
    k_gemm_hid_t<<<tile_blocks, T>>>(W2);
    k_gather<<<warp8_blocks, T>>>(b2);

    // ---- layer 3 ----
    k_gemm_hid_t<<<tile_blocks, T>>>(W3);
    k_gather<<<warp8_blocks, T>>>(b3);

    // ---- pooling ----
    k_zero_pool<<<(NG * HID + T - 1) / T, T>>>();
    k_pool<<<(NN + 127) / 128, HID>>>(bat);
    k_pooldiv<<<(NG * HID + T - 1) / T, T>>>();

    // ---- heads ----
    k_head<<<NG, LAT>>>(Wmu, bmu, Wlv, blv, out);
}

// round 14
// speedup vs baseline: 3.1619x; 1.0139x over previous
#include <cuda_runtime.h>
#include <cuda_bf16.h>
#include <mma.h>
using namespace nvcuda;

#define NN 100000
#define NE 3200000
#define NG 512
#define IN_DIM 29
#define HID 128
#define LAT 256

#define SCAN_B 512
#define NBLK ((NN + SCAN_B - 1) / SCAN_B)   // 196
#define TN 64                                // GEMM node tile

// ---------------- scratch (device globals; no allocation allowed) -------------
__device__ float g_dis[NN];
__device__ int   g_indeg[NN];
__device__ int   g_rowptr[NN + 1];
__device__ int   g_fill[NN];
__device__ int   g_col[NE];     // CSR: source node per incoming edge
__device__ float g_wt[NE];      // CSR: dis[src]*dis[dst] per incoming edge
__device__ int   g_bsum[NBLK];

__device__ float g_h[NN * HID];               // layer input (post-relu, fp32)
__device__ __nv_bfloat162 g_hb[NN * 64];      // layer input (bf16, HMMA A operand)
__device__ float g_hw[NN * HID];              // h @ W  (fp32, self-loop term)
__device__ __nv_bfloat162 g_hwh[NN * 64];     // h @ W  (bf16, neighbor gathers)
__device__ __nv_bfloat16 g_Wb[2 * HID * HID]; // W2, W3 in bf16
__device__ float g_sums[NG * HID];
__device__ float g_cnts[NG];
__device__ float g_pooled[NG * HID];

// ---------------- CSR build ---------------------------------------------------
__global__ void k_zero_deg() {
    int i = blockIdx.x * blockDim.x + threadIdx.x;
    if (i < NN) g_indeg[i] = 0;
}

__global__ void k_count(const int* __restrict__ dst) {
    int e = blockIdx.x * blockDim.x + threadIdx.x;
    if (e < NE) atomicAdd(&g_indeg[dst[e]], 1);
}

__global__ void k_dis() {   // also zeroes fill counters
    int i = blockIdx.x * blockDim.x + threadIdx.x;
    if (i < NN) {
        g_dis[i] = rsqrtf((float)g_indeg[i] + 1.0f);
        g_fill[i] = 0;
    }
}

__global__ void k_scan1() {
    __shared__ int sh[SCAN_B];
    int tid = threadIdx.x;
    int idx = blockIdx.x * SCAN_B + tid;
    int v = (idx < NN) ? g_indeg[idx] : 0;
    sh[tid] = v;
    __syncthreads();
    for (int off = 1; off < SCAN_B; off <<= 1) {
        int t = (tid >= off) ? sh[tid - off] : 0;
        __syncthreads();
        sh[tid] += t;
        __syncthreads();
    }
    if (idx < NN) g_rowptr[idx] = sh[tid] - v;
    if (tid == SCAN_B - 1) g_bsum[blockIdx.x] = sh[tid];
}

__global__ void k_scan2() {
    if (threadIdx.x == 0 && blockIdx.x == 0) {
        int run = 0;
        for (int i = 0; i < NBLK; i++) {
            int t = g_bsum[i];
            g_bsum[i] = run;
            run += t;
        }
    }
}

__global__ void k_scan3() {
    int idx = blockIdx.x * SCAN_B + threadIdx.x;
    if (idx < NN) g_rowptr[idx] += g_bsum[blockIdx.x];
    if (idx == 0) g_rowptr[NN] = NE;
}

__global__ void k_fill(const int* __restrict__ src, const int* __restrict__ dst) {
    int e = blockIdx.x * blockDim.x + threadIdx.x;
    if (e >= NE) return;
    int s = src[e];
    int d = dst[e];
    int pos = g_rowptr[d] + atomicAdd(&g_fill[d], 1);
    g_col[pos] = s;
    g_wt[pos]  = g_dis[s] * g_dis[d];
}

// ---------------- convert W2, W3 to bf16 --------------------------------------
__global__ void k_convW(const float* __restrict__ W2, const float* __restrict__ W3) {
    int i = blockIdx.x * blockDim.x + threadIdx.x;
    if (i < HID * HID) {
        g_Wb[i] = __float2bfloat16(W2[i]);
        g_Wb[HID * HID + i] = __float2bfloat16(W3[i]);
    }
}

// ---------------- epilogue helper: store fp32 + bf16 copies -------------------
__device__ __forceinline__ void store_hw(int node, int cg, float4 a) {
    ((float4*)g_hw)[node * 32 + cg] = a;
    g_hwh[node * 64 + cg * 2 + 0] = __float22bfloat162_rn(make_float2(a.x, a.y));
    g_hwh[node * 64 + cg * 2 + 1] = __float22bfloat162_rn(make_float2(a.z, a.w));
}

// ---------------- tiled GEMM: x[NN,29] @ W1[29,128] -> g_hw/g_hwh -------------
__global__ void k_gemm_in_t(const float* __restrict__ x, const float* __restrict__ W) {
    __shared__ float Hs[IN_DIM][TN];
    int base = blockIdx.x * TN;
    int t = threadIdx.x;
    for (int id = t; id < TN * IN_DIM; id += 256) {
        int n = id & 63;
        int kk = id >> 6;
        int node = base + n;
        Hs[kk][n] = (node < NN) ? __ldg(x + node * IN_DIM + kk) : 0.0f;
    }
    __syncthreads();

    int cg = t & 31;
    int ng = t >> 5;
    float4 acc[8] = {};
    const float4* W4 = (const float4*)W;
    #pragma unroll
    for (int k = 0; k < IN_DIM; k++) {
        float4 w = __ldg(W4 + k * 32 + cg);
        float hk[8];
        *(float4*)&hk[0] = *(const float4*)&Hs[k][ng * 8];
        *(float4*)&hk[4] = *(const float4*)&Hs[k][ng * 8 + 4];
        #pragma unroll
        for (int i = 0; i < 8; i++) {
            acc[i].x += hk[i] * w.x;
            acc[i].y += hk[i] * w.y;
            acc[i].z += hk[i] * w.z;
            acc[i].w += hk[i] * w.w;
        }
    }
    #pragma unroll
    for (int i = 0; i < 8; i++) {
        int node = base + ng * 8 + i;
        if (node < NN) store_hw(node, cg, acc[i]);
    }
}

// ---------------- HMMA GEMM: g_hb[NN,128](bf16) @ Wb[128,128] -> g_hw/g_hwh ---
__global__ void k_gemm_hid_wmma(int wsel) {
    __shared__ __nv_bfloat16 As[TN * HID];   // 16 KB
    __shared__ float Cs[TN * HID];           // 32 KB
    const __nv_bfloat16* Wb = g_Wb + wsel * HID * HID;
    int base = blockIdx.x * TN;
    int t = threadIdx.x;

    // load A tile (bf16 rows, 16 uint4 per row)
    const uint4* srcA = (const uint4*)g_hb;
    for (int id = t; id < TN * 16; id += 256) {
        int n = id >> 4;
        int node = base + n;
        uint4 v = (node < NN) ? srcA[node * 16 + (id & 15)] : make_uint4(0u, 0u, 0u, 0u);
        ((uint4*)As)[id] = v;
    }
    __syncthreads();

    int warp = t >> 5;
    int mt = warp & 3;             // m-tile row (16 rows)
    int nb = (warp >> 2) * 64;     // n base: 0 or 64
    wmma::fragment<wmma::accumulator, 16, 16, 16, float> c[4];
    #pragma unroll
    for (int i = 0; i < 4; i++) wmma::fill_fragment(c[i], 0.0f);

    #pragma unroll
    for (int k = 0; k < HID; k += 16) {
        wmma::fragment<wmma::matrix_a, 16, 16, 16, __nv_bfloat16, wmma::row_major> a;
        wmma::load_matrix_sync(a, As + mt * 16 * HID + k, HID);
        #pragma unroll
        for (int i = 0; i < 4; i++) {
            wmma::fragment<wmma::matrix_b, 16, 16, 16, __nv_bfloat16, wmma::row_major> bf;
            wmma::load_matrix_sync(bf, Wb + k * HID + nb + i * 16, HID);
            wmma::mma_sync(c[i], a, bf, c[i]);
        }
    }
    #pragma unroll
    for (int i = 0; i < 4; i++)
        wmma::store_matrix_sync(Cs + mt * 16 * HID + nb + i * 16, c[i], HID, wmma::mem_row_major);
    __syncthreads();

    // epilogue: write fp32 g_hw + bf16 g_hwh
    for (int id = t; id < TN * 32; id += 256) {
        int n = id >> 5;
        int q = id & 31;
        int node = base + n;
        if (node < NN) {
            float4 v = ((const float4*)Cs)[id];
            ((float4*)g_hw)[node * 32 + q] = v;
            g_hwh[node * 64 + q * 2 + 0] = __float22bfloat162_rn(make_float2(v.x, v.y));
            g_hwh[node * 64 + q * 2 + 1] = __float22bfloat162_rn(make_float2(v.z, v.w));
        }
    }
}

// ------- fused gather: h[d] = relu( sum_j w_j*hw[col_j] + dis^2*hw[d] + b ) ----
// neighbor rows read in bf16; self term + accumulate fp32; emits fp32 + bf16 h
__global__ void k_gather(const float* __restrict__ b) {
    int warp = threadIdx.x >> 5, lane = threadIdx.x & 31;
    int node = blockIdx.x * 8 + warp;
    if (node >= NN) return;

    float dd = g_dis[node];
    dd *= dd;
    float4 self = ((const float4*)g_hw)[node * 32 + lane];
    float4 bb = __ldg(((const float4*)b) + lane);
    float a0 = self.x * dd + bb.x;
    float a1 = self.y * dd + bb.y;
    float a2 = self.z * dd + bb.z;
    float a3 = self.w * dd + bb.w;

    const uint2* hwB = (const uint2*)g_hwh;
    int beg = g_rowptr[node], end = g_rowptr[node + 1];
    int j = beg;
    for (; j + 1 < end; j += 2) {
        int   s0 = __ldg(g_col + j);
        float w0 = __ldg(g_wt + j);
        int   s1 = __ldg(g_col + j + 1);
        float w1 = __ldg(g_wt + j + 1);
        uint2 u0 = hwB[s0 * 32 + lane];
        uint2 u1 = hwB[s1 * 32 + lane];
        float2 f00 = __bfloat1622float2(*(const __nv_bfloat162*)&u0.x);
        float2 f01 = __bfloat1622float2(*(const __nv_bfloat162*)&u0.y);
        float2 f10 = __bfloat1622float2(*(const __nv_bfloat162*)&u1.x);
        float2 f11 = __bfloat1622float2(*(const __nv_bfloat162*)&u1.y);
        a0 += w0 * f00.x + w1 * f10.x;
        a1 += w0 * f00.y + w1 * f10.y;
        a2 += w0 * f01.x + w1 * f11.x;
        a3 += w0 * f01.y + w1 * f11.y;
    }
    if (j < end) {
        int   s0 = __ldg(g_col + j);
        float w0 = __ldg(g_wt + j);
        uint2 u0 = hwB[s0 * 32 + lane];
        float2 f00 = __bfloat1622float2(*(const __nv_bfloat162*)&u0.x);
        float2 f01 = __bfloat1622float2(*(const __nv_bfloat162*)&u0.y);
        a0 += w0 * f00.x;
        a1 += w0 * f00.y;
        a2 += w0 * f01.x;
        a3 += w0 * f01.y;
    }

    float4 o;
    o.x = fmaxf(a0, 0.0f);
    o.y = fmaxf(a1, 0.0f);
    o.z = fmaxf(a2, 0.0f);
    o.w = fmaxf(a3, 0.0f);
    ((float4*)g_h)[node * 32 + lane] = o;
    g_hb[node * 64 + lane * 2 + 0] = __float22bfloat162_rn(make_float2(o.x, o.y));
    g_hb[node * 64 + lane * 2 + 1] = __float22bfloat162_rn(make_float2(o.z, o.w));
}

// ---------------- pooling (batch is sorted: run-length local accumulate) ------
__global__ void k_zero_pool() {
    int i = blockIdx.x * blockDim.x + threadIdx.x;
    if (i < NG * HID) g_sums[i] = 0.0f;
    if (i < NG) g_cnts[i] = 0.0f;
}

__global__ void k_pool(const int* __restrict__ batch) {
    const int CH = 128;
    int base = blockIdx.x * CH;
    int c = threadIdx.x;
    float acc = 0.0f;
    int cur = -1;
    for (int i = 0; i < CH; i++) {
        int node = base + i;
        if (node >= NN) break;
        int g = __ldg(batch + node);
        if (g != cur) {
            if (cur >= 0) atomicAdd(&g_sums[cur * HID + c], acc);
            cur = g; acc = 0.0f;
        }
        acc += g_h[node * HID + c];
    }
    if (cur >= 0) atomicAdd(&g_sums[cur * HID + c], acc);

    if (threadIdx.x == 0) {
        int cur2 = -1; float cnt = 0.0f;
        for (int i = 0; i < CH; i++) {
            int node = base + i;
            if (node >= NN) break;
            int g = __ldg(batch + node);
            if (g != cur2) {
                if (cur2 >= 0) atomicAdd(&g_cnts[cur2], cnt);
                cur2 = g; cnt = 0.0f;
            }
            cnt += 1.0f;
        }
        if (cur2 >= 0) atomicAdd(&g_cnts[cur2], cnt);
    }
}

__global__ void k_pooldiv() {
    int i = blockIdx.x * blockDim.x + threadIdx.x;
    if (i < NG * HID) {
        int g = i >> 7;
        g_pooled[i] = g_sums[i] / fmaxf(g_cnts[g], 1.0f);
    }
}

// ---------------- heads: mu = pooled@Wmu+bmu ; logvar = pooled@Wlv+blv --------
__global__ void k_head(const float* __restrict__ Wmu, const float* __restrict__ bmu,
                       const float* __restrict__ Wlv, const float* __restrict__ blv,
                       float* __restrict__ out) {
    int g = blockIdx.x;
    __shared__ float p[HID];
    for (int i = threadIdx.x; i < HID; i += blockDim.x) p[i] = g_pooled[g * HID + i];
    __syncthreads();
    int c = threadIdx.x;
    float am = __ldg(bmu + c);
    float al = __ldg(blv + c);
    #pragma unroll 8
    for (int k = 0; k < HID; k++) {
        float pv = p[k];
        am += pv * __ldg(Wmu + k * LAT + c);
        al += pv * __ldg(Wlv + k * LAT + c);
    }
    out[g * LAT + c] = am;
    out[NG * LAT + g * LAT + c] = al;
}

// ---------------- launcher ----------------------------------------------------
extern "C" void kernel_launch(void* const* d_in, const int* in_sizes, int n_in,
                              void* d_out, int out_size) {
    const float* x    = (const float*)d_in[0];
    const int*   ei   = (const int*)d_in[1];   // [2, NE] int32
    const int*   bat  = (const int*)d_in[2];   // [NN] int32
    const float* W1   = (const float*)d_in[3];
    const float* b1   = (const float*)d_in[4];
    const float* W2   = (const float*)d_in[5];
    const float* b2   = (const float*)d_in[6];
    const float* W3   = (const float*)d_in[7];
    const float* b3   = (const float*)d_in[8];
    const float* Wmu  = (const float*)d_in[9];
    const float* bmu  = (const float*)d_in[10];
    const float* Wlv  = (const float*)d_in[11];
    const float* blv  = (const float*)d_in[12];
    float* out = (float*)d_out;

    const int* src = ei;
    const int* dst = ei + NE;

    const int T = 256;
    const int node_blocks = (NN + T - 1) / T;
    const int edge_blocks = (NE + T - 1) / T;
    const int warp8_blocks = (NN + 7) / 8;
    const int tile_blocks = (NN + TN - 1) / TN;

    // ---- CSR build + weight conversion ----
    k_zero_deg<<<node_blocks, T>>>();
    k_count<<<edge_blocks, T>>>(dst);
    k_dis<<<node_blocks, T>>>();
    k_scan1<<<NBLK, SCAN_B>>>();
    k_scan2<<<1, 32>>>();
    k_scan3<<<NBLK, SCAN_B>>>();
    k_fill<<<edge_blocks, T>>>(src, dst);
    k_convW<<<(HID * HID + T - 1) / T, T>>>(W2, W3);

    // ---- layer 1 (29 -> 128, fp32 SIMT) ----
    k_gemm_in_t<<<tile_blocks, T>>>(x, W1);
    k_gather<<<warp8_blocks, T>>>(b1);

    // ---- layer 2 (HMMA) ----
    k_gemm_hid_wmma<<<tile_blocks, T>>>(0);
    k_gather<<<warp8_blocks, T>>>(b2);

    // ---- layer 3 (HMMA) ----
    k_gemm_hid_wmma<<<tile_blocks, T>>>(1);
    k_gather<<<warp8_blocks, T>>>(b3);

    // ---- pooling ----
    k_zero_pool<<<(NG * HID + T - 1) / T, T>>>();
    k_pool<<<(NN + 127) / 128, HID>>>(bat);
    k_pooldiv<<<(NG * HID + T - 1) / T, T>>>();

    // ---- heads ----
    k_head<<<NG, LAT>>>(Wmu, bmu, Wlv, blv, out);
}